// round 13
// baseline (speedup 1.0000x reference)
#include <cuda_runtime.h>
#include <cuda_fp16.h>
#include <math.h>
#include <math_constants.h>

#define B_SZ   2
#define S_LEN  2048
#define D_MOD  1024
#define NH     16
#define DK     64
#define M_TOT  (B_SZ * S_LEN)   // 4096

// Scratch (allocation-free rule: __device__ globals). All fp16, NATURAL k-order
// (ldmatrix performs the fragment distribution).
__device__ __half g_X [M_TOT * D_MOD];
__device__ __half g_Wq[D_MOD * D_MOD];
__device__ __half g_Wk[D_MOD * D_MOD];
__device__ __half g_Wv[D_MOD * D_MOD];
__device__ __half g_Wo[D_MOD * D_MOD];
__device__ __half g_Q [M_TOT * D_MOD];
__device__ __half g_K [M_TOT * D_MOD];
__device__ __half g_VT[M_TOT * D_MOD];   // V transposed [b,h,d,s]
__device__ __half g_AO[M_TOT * D_MOD];   // attention out
__device__ float  g_freq[512];           // RoPE inv freqs per even col

__device__ __forceinline__ unsigned h2u(__half2 v) { return *(unsigned*)&v; }

__device__ __forceinline__ void mma16(float* d,
                                      unsigned a0, unsigned a1, unsigned a2, unsigned a3,
                                      unsigned b0, unsigned b1) {
    asm volatile(
        "mma.sync.aligned.m16n8k16.row.col.f32.f16.f16.f32 "
        "{%0,%1,%2,%3}, {%4,%5,%6,%7}, {%8,%9}, {%0,%1,%2,%3};\n"
        : "+f"(d[0]), "+f"(d[1]), "+f"(d[2]), "+f"(d[3])
        : "r"(a0), "r"(a1), "r"(a2), "r"(a3), "r"(b0), "r"(b1));
}

__device__ __forceinline__ void ldsm4(unsigned& r0, unsigned& r1,
                                      unsigned& r2, unsigned& r3, unsigned addr) {
    asm volatile("ldmatrix.sync.aligned.m8n8.x4.shared.b16 {%0,%1,%2,%3}, [%4];"
                 : "=r"(r0), "=r"(r1), "=r"(r2), "=r"(r3) : "r"(addr));
}

__device__ __forceinline__ void cp16(void* smem, const void* gmem) {
    unsigned s = (unsigned)__cvta_generic_to_shared(smem);
    asm volatile("cp.async.cg.shared.global [%0], [%1], 16;" :: "r"(s), "l"(gmem));
}
#define CP_COMMIT() asm volatile("cp.async.commit_group;")
#define CP_WAIT0()  asm volatile("cp.async.wait_group 0;")

__device__ __forceinline__ unsigned s2u(const void* p) {
    unsigned a;
    asm("{ .reg .u64 t; cvta.to.shared.u64 t, %1; cvt.u32.u64 %0, t; }" : "=r"(a) : "l"(p));
    return a;
}

// pack two f32 -> f16x2 (lo = a, hi = b)
__device__ __forceinline__ unsigned pack_h2(float a, float b) {
    unsigned u;
    asm("cvt.rn.f16x2.f32 %0, %1, %2;" : "=r"(u) : "f"(b), "f"(a));
    return u;
}
__device__ __forceinline__ unsigned ex2_h2(unsigned t) {
    unsigned p;
    asm("ex2.approx.f16x2 %0, %1;" : "=r"(p) : "r"(t));
    return p;
}
__device__ __forceinline__ float ex2f(float x) {
    float r;
    asm("ex2.approx.f32 %0, %1;" : "=f"(r) : "f"(x));
    return r;
}

// ============================================================================
// Pre-round fp32 -> fp16 (rn), natural order. Also fills freq table.
// ============================================================================
__global__ __launch_bounds__(256)
void preround(const float* __restrict__ x,
              const float* __restrict__ wq, const float* __restrict__ wk,
              const float* __restrict__ wv, const float* __restrict__ wo)
{
    if (blockIdx.x == 0 && threadIdx.x < 256) {
        #pragma unroll
        for (int q = 0; q < 2; q++) {
            int j = threadIdx.x + q * 256;
            g_freq[j] = (float)exp2((double)(2 * j) * (-13.287712379549449 / 1024.0));
        }
    }
    int gidx = blockIdx.x * blockDim.x + threadIdx.x;   // 16-float group
    const float* src; __half* dst; int off;
    if (gidx < 262144) { src = x; dst = g_X; off = gidx; }
    else {
        int t = gidx - 262144; int w = t >> 16; off = t & 65535;
        src = (w == 0) ? wq : (w == 1) ? wk : (w == 2) ? wv : wo;
        dst = (w == 0) ? g_Wq : (w == 1) ? g_Wk : (w == 2) ? g_Wv : g_Wo;
    }
    const float4* s4 = (const float4*)src + (size_t)off * 4;
    float4 f0 = s4[0], f1 = s4[1], f2 = s4[2], f3 = s4[3];
    uint4 u0, u1;
    u0.x = h2u(__floats2half2_rn(f0.x, f0.y));
    u0.y = h2u(__floats2half2_rn(f0.z, f0.w));
    u0.z = h2u(__floats2half2_rn(f1.x, f1.y));
    u0.w = h2u(__floats2half2_rn(f1.z, f1.w));
    u1.x = h2u(__floats2half2_rn(f2.x, f2.y));
    u1.y = h2u(__floats2half2_rn(f2.z, f2.w));
    u1.z = h2u(__floats2half2_rn(f3.x, f3.y));
    u1.w = h2u(__floats2half2_rn(f3.z, f3.w));
    uint4* d4 = (uint4*)(dst + (size_t)off * 16);
    d4[0] = u0;
    d4[1] = u1;
}

// ============================================================================
// FP16 GEMM: C = A @ W^T. CTA tile 128x64, K-stage 64 halves, 16 iters.
// 8 warps (4m x 2n), warp tile 32x32 (acc = 32 regs) -> 3 CTAs/SM = 24 warps,
// 3-way independent-CTA interleave hides the per-CTA barrier convoy.
// m16n8k16 + ldmatrix (144B stride, conflict-free), 2-stage cp.async.
// mode 0: z<2 -> RoPE (Q/K, __sincosf); z==2 -> V transpose. mode 1: fp32 out.
// ============================================================================
#define SROWH 72
#define GSTGH (192 * SROWH)                    // 13824 halves per stage (A128+B64)
#define GEMM_SMEM_BYTES (2 * GSTGH * 2)        // 55296

__global__ __launch_bounds__(256, 3)
void gemm_f16(const __half* __restrict__ A,
              const __half* __restrict__ W0, const __half* __restrict__ W1,
              const __half* __restrict__ W2,
              void* __restrict__ C0v, void* __restrict__ C1v, void* __restrict__ C2v,
              const int* __restrict__ tokpos, int mode)
{
    const __half* W = W0; void* Cv = C0v;
    if (blockIdx.z == 1) { W = W1; Cv = C1v; }
    else if (blockIdx.z == 2) { W = W2; Cv = C2v; }

    extern __shared__ __align__(16) __half smh[];
    const unsigned sbase = s2u(smh);

    const int tid  = threadIdx.x;
    const int lane = tid & 31;
    const int warp = tid >> 5;
    const int wm = warp >> 1;   // 0..3
    const int wn = warp & 1;    // 0..1
    const int g = lane >> 2;    // 0..7
    const int c = lane & 3;     // 0..3
    const int m0 = blockIdx.y * 128;
    const int n0 = blockIdx.x * 64;

    const int crow = tid >> 3;            // 0..31
    const int cc8  = (tid & 7) << 3;      // 0..56 (halves)

    // ldmatrix per-lane offsets (bytes)
    const unsigned aOff = (unsigned)((lane & 15) * 144 + (lane >> 4) * 16);
    const unsigned bOff = (unsigned)(((lane & 7) + ((lane >> 4) << 3)) * 144
                                     + ((lane >> 3) & 1) * 16);

    float acc[2][4][4];
    #pragma unroll
    for (int i = 0; i < 2; i++)
        #pragma unroll
        for (int j = 0; j < 4; j++)
            #pragma unroll
            for (int r = 0; r < 4; r++) acc[i][j][r] = 0.f;

    {
        __half* Xs = smh;
        __half* Ws = smh + 128 * SROWH;
        #pragma unroll
        for (int p = 0; p < 4; p++) {
            int row = crow + p * 32;
            cp16(&Xs[row * SROWH + cc8], A + (size_t)(m0 + row) * D_MOD + cc8);
        }
        #pragma unroll
        for (int p = 0; p < 2; p++) {
            int row = crow + p * 32;
            cp16(&Ws[row * SROWH + cc8], W + (size_t)(n0 + row) * D_MOD + cc8);
        }
        CP_COMMIT();
    }

    const int NIT = D_MOD / 64;   // 16
    for (int it = 0; it < NIT; it++) {
        CP_WAIT0();
        __syncthreads();
        if (it + 1 < NIT) {
            int k0 = (it + 1) * 64;
            __half* Xs = smh + ((it + 1) & 1) * GSTGH;
            __half* Ws = Xs + 128 * SROWH;
            #pragma unroll
            for (int p = 0; p < 4; p++) {
                int row = crow + p * 32;
                cp16(&Xs[row * SROWH + cc8], A + (size_t)(m0 + row) * D_MOD + k0 + cc8);
            }
            #pragma unroll
            for (int p = 0; p < 2; p++) {
                int row = crow + p * 32;
                cp16(&Ws[row * SROWH + cc8], W + (size_t)(n0 + row) * D_MOD + k0 + cc8);
            }
            CP_COMMIT();
        }

        const unsigned sA = sbase + (it & 1) * (GSTGH * 2);
        const unsigned sB = sA + 128 * 144;

        #pragma unroll
        for (int ks = 0; ks < 4; ks++) {
            unsigned a[2][4], b[2][4];
            #pragma unroll
            for (int mt = 0; mt < 2; mt++)
                ldsm4(a[mt][0], a[mt][1], a[mt][2], a[mt][3],
                      sA + (wm * 32 + mt * 16) * 144 + ks * 32 + aOff);
            #pragma unroll
            for (int np = 0; np < 2; np++)
                ldsm4(b[np][0], b[np][1], b[np][2], b[np][3],
                      sB + (wn * 32 + np * 16) * 144 + ks * 32 + bOff);
            #pragma unroll
            for (int mt = 0; mt < 2; mt++) {
                mma16(acc[mt][0], a[mt][0], a[mt][1], a[mt][2], a[mt][3], b[0][0], b[0][1]);
                mma16(acc[mt][1], a[mt][0], a[mt][1], a[mt][2], a[mt][3], b[0][2], b[0][3]);
                mma16(acc[mt][2], a[mt][0], a[mt][1], a[mt][2], a[mt][3], b[1][0], b[1][1]);
                mma16(acc[mt][3], a[mt][0], a[mt][1], a[mt][2], a[mt][3], b[1][2], b[1][3]);
            }
        }
    }
    __syncthreads();

    #pragma unroll
    for (int mt = 0; mt < 2; mt++) {
        int r0 = m0 + wm * 32 + mt * 16 + g;
        int r1 = r0 + 8;
        if (mode == 1) {
            float* C = (float*)Cv;
            #pragma unroll
            for (int nt = 0; nt < 4; nt++) {
                int col = n0 + wn * 32 + nt * 8 + c * 2;
                *(float2*)(C + (size_t)r0 * D_MOD + col) = make_float2(acc[mt][nt][0], acc[mt][nt][1]);
                *(float2*)(C + (size_t)r1 * D_MOD + col) = make_float2(acc[mt][nt][2], acc[mt][nt][3]);
            }
        } else if (blockIdx.z < 2) {
            // Q/K: RoPE on natural adjacent pairs -> half2 store (fast sincos)
            __half* C = (__half*)Cv;
            float pf0 = (float)tokpos[r0], pf1 = (float)tokpos[r1];
            #pragma unroll
            for (int nt = 0; nt < 4; nt++) {
                int col = n0 + wn * 32 + nt * 8 + 2 * c;
                float x00 = acc[mt][nt][0], x01 = acc[mt][nt][1];
                float x10 = acc[mt][nt][2], x11 = acc[mt][nt][3];
                float freq = g_freq[col >> 1];
                float s0, cs0, s1, cs1;
                __sincosf(pf0 * freq, &s0, &cs0);
                __sincosf(pf1 * freq, &s1, &cs1);
                float y00 = x00 * cs0 - x01 * s0, y01 = x00 * s0 + x01 * cs0;
                float y10 = x10 * cs1 - x11 * s1, y11 = x10 * s1 + x11 * cs1;
                *(__half2*)(C + (size_t)r0 * D_MOD + col) = __floats2half2_rn(y00, y01);
                *(__half2*)(C + (size_t)r1 * D_MOD + col) = __floats2half2_rn(y10, y11);
            }
        } else {
            // V transpose: g_VT[((b*16+h)*64 + d)*2048 + s]
            __half* C = (__half*)Cv;
            int bb = r0 >> 11;
            int s  = r0 & 2047;
            #pragma unroll
            for (int nt = 0; nt < 4; nt++) {
                int n = n0 + wn * 32 + nt * 8 + 2 * c;
                int h = n >> 6, d = n & 63;
                size_t base = ((size_t)((bb << 4) | h) * 64 + d) * 2048;
                C[base        + s    ] = __float2half_rn(acc[mt][nt][0]);
                C[base + 2048 + s    ] = __float2half_rn(acc[mt][nt][1]);   // d+1
                C[base        + s + 8] = __float2half_rn(acc[mt][nt][2]);   // s+8
                C[base + 2048 + s + 8] = __float2half_rn(acc[mt][nt][3]);
            }
        }
    }
}

// ============================================================================
// Fused causal flash attention (round-12 proven). P in registers; Q staged
// through K[1]; fp16 mma + ldmatrix; log2-domain ex2.f16x2 softmax.
// 128 threads, 64 q/CTA, 4 CTAs/SM. smem = 36864 B.
// ============================================================================
#define KSTRH 72
#define TILEH (64 * KSTRH)                     // 4608 halves / tile
#define FK0 0
#define FK1 TILEH
#define FV0 (2 * TILEH)
#define FV1 (3 * TILEH)
#define FLASH_SMEM_BYTES (4 * TILEH * 2)       // 36864

__global__ __launch_bounds__(128, 4)
void flash_attn()
{
    extern __shared__ __align__(16) __half smf[];
    const unsigned sbase = s2u(smf);
    const int tid  = threadIdx.x;
    const int lane = tid & 31;
    const int warp = tid >> 5;
    const int g = lane >> 2;
    const int c = lane & 3;
    const int qt = (S_LEN / 64 - 1) - blockIdx.x;   // heavy tiles first
    const int bh = blockIdx.y;
    const int b = bh >> 4, h = bh & 15;

    const __half* Qg  = g_Q  + ((size_t)(b * S_LEN + qt * 64)) * D_MOD + h * 64;
    const __half* Kg  = g_K  + ((size_t)(b * S_LEN)) * D_MOD + h * 64;
    const __half* VTg = g_VT + ((size_t)((b * 16 + h) * 64)) * 2048;

    const int crow = tid >> 3;          // 0..15
    const int cc8  = (tid & 7) << 3;    // 0..56

    const unsigned aOff = (unsigned)((lane & 15) * 144 + (lane >> 4) * 16);
    const unsigned bOff = (unsigned)(((lane & 7) + ((lane >> 4) << 3)) * 144
                                     + ((lane >> 3) & 1) * 16);

    // prologue: cp.async K0/V0; Q staged into K[1] with plain stores
    #pragma unroll
    for (int p = 0; p < 4; p++) {
        int row = crow + p * 16;
        cp16(&smf[FK0 + row * KSTRH + cc8], Kg  + (size_t)row * D_MOD + cc8);
        cp16(&smf[FV0 + row * KSTRH + cc8], VTg + (size_t)row * 2048 + cc8);
        *(uint4*)&smf[FK1 + row * KSTRH + cc8] =
            *(const uint4*)(Qg + (size_t)row * D_MOD + cc8);
    }
    CP_COMMIT();
    __syncthreads();

    // hoist Q fragments via ldmatrix from K[1] (overwritten at kt=1 prefetch)
    const int qrow0 = warp * 16 + g;
    const int qrow1 = qrow0 + 8;
    unsigned qa[4][4];
    #pragma unroll
    for (int ks = 0; ks < 4; ks++)
        ldsm4(qa[ks][0], qa[ks][1], qa[ks][2], qa[ks][3],
              sbase + FK1 * 2 + (warp * 16) * 144 + ks * 32 + aOff);

    const float CSC = 0.18033688011112042f;   // log2(e)/8
    float m0f = -CUDART_INF_F, m1f = -CUDART_INF_F;
    float l0 = 0.f, l1 = 0.f;
    float o[8][4];
    #pragma unroll
    for (int dt = 0; dt < 8; dt++)
        #pragma unroll
        for (int r = 0; r < 4; r++) o[dt][r] = 0.f;

    for (int kt = 0; kt <= qt; kt++) {
        CP_WAIT0();
        __syncthreads();
        if (kt < qt) {
            int st = (kt + 1) & 1;
            #pragma unroll
            for (int p = 0; p < 4; p++) {
                int row = crow + p * 16;
                cp16(&smf[(st ? FK1 : FK0) + row * KSTRH + cc8],
                     Kg + (size_t)((kt + 1) * 64 + row) * D_MOD + cc8);
                cp16(&smf[(st ? FV1 : FV0) + row * KSTRH + cc8],
                     VTg + (size_t)row * 2048 + (kt + 1) * 64 + cc8);
            }
            CP_COMMIT();
        }
        const unsigned sK = sbase + ((kt & 1) ? FK1 : FK0) * 2;
        const unsigned sV = sbase + ((kt & 1) ? FV1 : FV0) * 2;

        // S = Q @ K^T (raw scores)
        float sacc[8][4];
        #pragma unroll
        for (int nt = 0; nt < 8; nt++)
            #pragma unroll
            for (int r = 0; r < 4; r++) sacc[nt][r] = 0.f;

        #pragma unroll
        for (int ks = 0; ks < 4; ks++) {
            #pragma unroll
            for (int np = 0; np < 4; np++) {
                unsigned b0, b1, b2, b3;
                ldsm4(b0, b1, b2, b3, sK + (np * 16) * 144 + ks * 32 + bOff);
                mma16(sacc[np * 2],     qa[ks][0], qa[ks][1], qa[ks][2], qa[ks][3], b0, b1);
                mma16(sacc[np * 2 + 1], qa[ks][0], qa[ks][1], qa[ks][2], qa[ks][3], b2, b3);
            }
        }

        if (kt == qt) {
            #pragma unroll
            for (int nt = 0; nt < 8; nt++) {
                int k0c = nt * 8 + c * 2, k1c = k0c + 1;
                if (k0c > qrow0) sacc[nt][0] = -CUDART_INF_F;
                if (k1c > qrow0) sacc[nt][1] = -CUDART_INF_F;
                if (k0c > qrow1) sacc[nt][2] = -CUDART_INF_F;
                if (k1c > qrow1) sacc[nt][3] = -CUDART_INF_F;
            }
        }

        float r0 = -CUDART_INF_F, r1 = -CUDART_INF_F;
        #pragma unroll
        for (int nt = 0; nt < 8; nt++) {
            r0 = fmaxf(r0, fmaxf(sacc[nt][0], sacc[nt][1]));
            r1 = fmaxf(r1, fmaxf(sacc[nt][2], sacc[nt][3]));
        }
        r0 = fmaxf(r0, __shfl_xor_sync(0xffffffffu, r0, 1));
        r0 = fmaxf(r0, __shfl_xor_sync(0xffffffffu, r0, 2));
        r1 = fmaxf(r1, __shfl_xor_sync(0xffffffffu, r1, 1));
        r1 = fmaxf(r1, __shfl_xor_sync(0xffffffffu, r1, 2));
        float mn0 = fmaxf(m0f, r0 * CSC), mn1 = fmaxf(m1f, r1 * CSC);
        float al0 = ex2f(m0f - mn0), al1 = ex2f(m1f - mn1);
        m0f = mn0; m1f = mn1;

        // P in registers: pp[nt][0] = (p00,p01) row g; pp[nt][1] = row g+8
        unsigned pp[8][2];
        float rs0 = 0.f, rs1 = 0.f;
        #pragma unroll
        for (int nt = 0; nt < 8; nt++) {
            float t00 = fmaf(sacc[nt][0], CSC, -mn0);
            float t01 = fmaf(sacc[nt][1], CSC, -mn0);
            float t10 = fmaf(sacc[nt][2], CSC, -mn1);
            float t11 = fmaf(sacc[nt][3], CSC, -mn1);
            pp[nt][0] = ex2_h2(pack_h2(t00, t01));
            pp[nt][1] = ex2_h2(pack_h2(t10, t11));
            float2 f0 = __half22float2(*(__half2*)&pp[nt][0]);
            float2 f1 = __half22float2(*(__half2*)&pp[nt][1]);
            rs0 += f0.x + f0.y;
            rs1 += f1.x + f1.y;
        }
        l0 = l0 * al0 + rs0;
        l1 = l1 * al1 + rs1;
        #pragma unroll
        for (int dt = 0; dt < 8; dt++) {
            o[dt][0] *= al0; o[dt][1] *= al0;
            o[dt][2] *= al1; o[dt][3] *= al1;
        }

        // O += P @ V (A-frags directly from pp)
        #pragma unroll
        for (int ks = 0; ks < 4; ks++) {
            #pragma unroll
            for (int dp = 0; dp < 4; dp++) {
                unsigned v0, v1, v2, v3;
                ldsm4(v0, v1, v2, v3, sV + (dp * 16) * 144 + ks * 32 + bOff);
                mma16(o[dp * 2],     pp[2*ks][0], pp[2*ks][1],
                                     pp[2*ks+1][0], pp[2*ks+1][1], v0, v1);
                mma16(o[dp * 2 + 1], pp[2*ks][0], pp[2*ks][1],
                                     pp[2*ks+1][0], pp[2*ks+1][1], v2, v3);
            }
        }
    }

    l0 += __shfl_xor_sync(0xffffffffu, l0, 1);
    l0 += __shfl_xor_sync(0xffffffffu, l0, 2);
    l1 += __shfl_xor_sync(0xffffffffu, l1, 1);
    l1 += __shfl_xor_sync(0xffffffffu, l1, 2);
    float inv0 = 1.f / l0, inv1 = 1.f / l1;

    __half* Og = g_AO + ((size_t)(b * S_LEN + qt * 64)) * D_MOD + h * 64;
    #pragma unroll
    for (int dt = 0; dt < 8; dt++) {
        int pos = dt * 8 + 2 * c;
        *(__half2*)(Og + (size_t)qrow0 * D_MOD + pos) =
            __floats2half2_rn(o[dt][0] * inv0, o[dt][1] * inv0);
        *(__half2*)(Og + (size_t)qrow1 * D_MOD + pos) =
            __floats2half2_rn(o[dt][2] * inv1, o[dt][3] * inv1);
    }
}

// ============================================================================
extern "C" void kernel_launch(void* const* d_in, const int* in_sizes, int n_in,
                              void* d_out, int out_size)
{
    (void)in_sizes; (void)n_in; (void)out_size;
    const float* x  = (const float*)d_in[0];
    const int*   tp = (const int*)d_in[1];
    const float* wq = (const float*)d_in[2];
    const float* wk = (const float*)d_in[3];
    const float* wv = (const float*)d_in[4];
    const float* wo = (const float*)d_in[5];
    float* out = (float*)d_out;

    __half *xptr, *wqp, *wkp, *wvp, *wop, *qptr, *kptr, *vtptr, *aoptr;
    cudaGetSymbolAddress((void**)&xptr,  g_X);
    cudaGetSymbolAddress((void**)&wqp,   g_Wq);
    cudaGetSymbolAddress((void**)&wkp,   g_Wk);
    cudaGetSymbolAddress((void**)&wvp,   g_Wv);
    cudaGetSymbolAddress((void**)&wop,   g_Wo);
    cudaGetSymbolAddress((void**)&qptr,  g_Q);
    cudaGetSymbolAddress((void**)&kptr,  g_K);
    cudaGetSymbolAddress((void**)&vtptr, g_VT);
    cudaGetSymbolAddress((void**)&aoptr, g_AO);

    cudaFuncSetAttribute(gemm_f16, cudaFuncAttributeMaxDynamicSharedMemorySize,
                         GEMM_SMEM_BYTES);
    cudaFuncSetAttribute(flash_attn, cudaFuncAttributeMaxDynamicSharedMemorySize,
                         FLASH_SMEM_BYTES);

    // 0) fp32 -> fp16 + freq table
    preround<<<2048, 256>>>(x, wq, wk, wv, wo);

    // 1) Q/K/V projections (+ fused RoPE on Q,K; V stored transposed)
    dim3 gq(D_MOD / 64, M_TOT / 128, 3);
    gemm_f16<<<gq, 256, GEMM_SMEM_BYTES>>>(xptr, wqp, wkp, wvp,
                                           qptr, kptr, vtptr, tp, 0);

    // 2) fused causal attention
    flash_attn<<<dim3(S_LEN / 64, B_SZ * NH), 128, FLASH_SMEM_BYTES>>>();

    // 3) output projection (fp32 out)
    dim3 go(D_MOD / 64, M_TOT / 128, 1);
    gemm_f16<<<go, 256, GEMM_SMEM_BYTES>>>(aoptr, wop, wop, wop,
                                           out, out, out, nullptr, 1);
}

// round 14
// speedup vs baseline: 1.0557x; 1.0557x over previous
#include <cuda_runtime.h>
#include <cuda_fp16.h>
#include <math.h>
#include <math_constants.h>

#define B_SZ   2
#define S_LEN  2048
#define D_MOD  1024
#define NH     16
#define DK     64
#define M_TOT  (B_SZ * S_LEN)   // 4096

// Scratch (allocation-free rule: __device__ globals). All fp16, NATURAL k-order
// (ldmatrix performs the fragment distribution).
__device__ __half g_X [M_TOT * D_MOD];
__device__ __half g_Wq[D_MOD * D_MOD];
__device__ __half g_Wk[D_MOD * D_MOD];
__device__ __half g_Wv[D_MOD * D_MOD];
__device__ __half g_Wo[D_MOD * D_MOD];
__device__ __half g_Q [M_TOT * D_MOD];
__device__ __half g_K [M_TOT * D_MOD];
__device__ __half g_VT[M_TOT * D_MOD];   // V transposed [b,h,d,s]
__device__ __half g_AO[M_TOT * D_MOD];   // attention out
__device__ float  g_freq[512];           // RoPE inv freqs per even col

__device__ __forceinline__ unsigned h2u(__half2 v) { return *(unsigned*)&v; }

__device__ __forceinline__ void mma16(float* d,
                                      unsigned a0, unsigned a1, unsigned a2, unsigned a3,
                                      unsigned b0, unsigned b1) {
    asm volatile(
        "mma.sync.aligned.m16n8k16.row.col.f32.f16.f16.f32 "
        "{%0,%1,%2,%3}, {%4,%5,%6,%7}, {%8,%9}, {%0,%1,%2,%3};\n"
        : "+f"(d[0]), "+f"(d[1]), "+f"(d[2]), "+f"(d[3])
        : "r"(a0), "r"(a1), "r"(a2), "r"(a3), "r"(b0), "r"(b1));
}

__device__ __forceinline__ void ldsm4(unsigned& r0, unsigned& r1,
                                      unsigned& r2, unsigned& r3, unsigned addr) {
    asm volatile("ldmatrix.sync.aligned.m8n8.x4.shared.b16 {%0,%1,%2,%3}, [%4];"
                 : "=r"(r0), "=r"(r1), "=r"(r2), "=r"(r3) : "r"(addr));
}

__device__ __forceinline__ void cp16(void* smem, const void* gmem) {
    unsigned s = (unsigned)__cvta_generic_to_shared(smem);
    asm volatile("cp.async.cg.shared.global [%0], [%1], 16;" :: "r"(s), "l"(gmem));
}
#define CP_COMMIT() asm volatile("cp.async.commit_group;")
#define CP_WAIT0()  asm volatile("cp.async.wait_group 0;")

__device__ __forceinline__ unsigned s2u(const void* p) {
    unsigned a;
    asm("{ .reg .u64 t; cvta.to.shared.u64 t, %1; cvt.u32.u64 %0, t; }" : "=r"(a) : "l"(p));
    return a;
}

// pack two f32 -> f16x2 (lo = a, hi = b)
__device__ __forceinline__ unsigned pack_h2(float a, float b) {
    unsigned u;
    asm("cvt.rn.f16x2.f32 %0, %1, %2;" : "=r"(u) : "f"(b), "f"(a));
    return u;
}
__device__ __forceinline__ unsigned ex2_h2(unsigned t) {
    unsigned p;
    asm("ex2.approx.f16x2 %0, %1;" : "=r"(p) : "r"(t));
    return p;
}
__device__ __forceinline__ float ex2f(float x) {
    float r;
    asm("ex2.approx.f32 %0, %1;" : "=f"(r) : "f"(x));
    return r;
}

// ============================================================================
// Pre-round fp32 -> fp16 (rn), natural order. Also fills freq table.
// ============================================================================
__global__ __launch_bounds__(256)
void preround(const float* __restrict__ x,
              const float* __restrict__ wq, const float* __restrict__ wk,
              const float* __restrict__ wv, const float* __restrict__ wo)
{
    if (blockIdx.x == 0 && threadIdx.x < 256) {
        #pragma unroll
        for (int q = 0; q < 2; q++) {
            int j = threadIdx.x + q * 256;
            g_freq[j] = (float)exp2((double)(2 * j) * (-13.287712379549449 / 1024.0));
        }
    }
    int gidx = blockIdx.x * blockDim.x + threadIdx.x;   // 16-float group
    const float* src; __half* dst; int off;
    if (gidx < 262144) { src = x; dst = g_X; off = gidx; }
    else {
        int t = gidx - 262144; int w = t >> 16; off = t & 65535;
        src = (w == 0) ? wq : (w == 1) ? wk : (w == 2) ? wv : wo;
        dst = (w == 0) ? g_Wq : (w == 1) ? g_Wk : (w == 2) ? g_Wv : g_Wo;
    }
    const float4* s4 = (const float4*)src + (size_t)off * 4;
    float4 f0 = s4[0], f1 = s4[1], f2 = s4[2], f3 = s4[3];
    uint4 u0, u1;
    u0.x = h2u(__floats2half2_rn(f0.x, f0.y));
    u0.y = h2u(__floats2half2_rn(f0.z, f0.w));
    u0.z = h2u(__floats2half2_rn(f1.x, f1.y));
    u0.w = h2u(__floats2half2_rn(f1.z, f1.w));
    u1.x = h2u(__floats2half2_rn(f2.x, f2.y));
    u1.y = h2u(__floats2half2_rn(f2.z, f2.w));
    u1.z = h2u(__floats2half2_rn(f3.x, f3.y));
    u1.w = h2u(__floats2half2_rn(f3.z, f3.w));
    uint4* d4 = (uint4*)(dst + (size_t)off * 16);
    d4[0] = u0;
    d4[1] = u1;
}

// ============================================================================
// FP16 GEMM: C = A @ W^T. CTA tile 128x64, 4 warps (2m x 2n), warp tile 64x32
// (the PROVEN shape), m16n8k16 + ldmatrix (144B stride, conflict-free).
// 2-stage cp.async, K-stage 64 halves, 16 iters. 4 CTAs/SM (regs<=128,
// smem 55.3KB) — flash-style independent-CTA interleave hides barriers.
// mode 0: z<2 -> RoPE (Q/K, __sincosf); z==2 -> V transpose. mode 1: fp32 out.
// ============================================================================
#define SROWH 72
#define GSTGH (192 * SROWH)                    // 13824 halves per stage (A128+B64)
#define GEMM_SMEM_BYTES (2 * GSTGH * 2)        // 55296

__global__ __launch_bounds__(128, 4)
void gemm_f16(const __half* __restrict__ A,
              const __half* __restrict__ W0, const __half* __restrict__ W1,
              const __half* __restrict__ W2,
              void* __restrict__ C0v, void* __restrict__ C1v, void* __restrict__ C2v,
              const int* __restrict__ tokpos, int mode)
{
    const __half* W = W0; void* Cv = C0v;
    if (blockIdx.z == 1) { W = W1; Cv = C1v; }
    else if (blockIdx.z == 2) { W = W2; Cv = C2v; }

    extern __shared__ __align__(16) __half smh[];
    const unsigned sbase = s2u(smh);

    const int tid  = threadIdx.x;
    const int lane = tid & 31;
    const int warp = tid >> 5;   // 0..3
    const int wm = warp >> 1;    // 0..1
    const int wn = warp & 1;     // 0..1
    const int g = lane >> 2;     // 0..7
    const int c = lane & 3;      // 0..3
    const int m0 = blockIdx.y * 128;
    const int n0 = blockIdx.x * 64;

    const int crow = tid >> 3;            // 0..15
    const int cc8  = (tid & 7) << 3;      // 0..56 (halves)

    // ldmatrix per-lane offsets (bytes)
    const unsigned aOff = (unsigned)((lane & 15) * 144 + (lane >> 4) * 16);
    const unsigned bOff = (unsigned)(((lane & 7) + ((lane >> 4) << 3)) * 144
                                     + ((lane >> 3) & 1) * 16);

    float acc[4][4][4];
    #pragma unroll
    for (int i = 0; i < 4; i++)
        #pragma unroll
        for (int j = 0; j < 4; j++)
            #pragma unroll
            for (int r = 0; r < 4; r++) acc[i][j][r] = 0.f;

    {
        __half* Xs = smh;
        __half* Ws = smh + 128 * SROWH;
        #pragma unroll
        for (int p = 0; p < 8; p++) {
            int row = crow + p * 16;
            cp16(&Xs[row * SROWH + cc8], A + (size_t)(m0 + row) * D_MOD + cc8);
        }
        #pragma unroll
        for (int p = 0; p < 4; p++) {
            int row = crow + p * 16;
            cp16(&Ws[row * SROWH + cc8], W + (size_t)(n0 + row) * D_MOD + cc8);
        }
        CP_COMMIT();
    }

    const int NIT = D_MOD / 64;   // 16
    for (int it = 0; it < NIT; it++) {
        CP_WAIT0();
        __syncthreads();
        if (it + 1 < NIT) {
            int k0 = (it + 1) * 64;
            __half* Xs = smh + ((it + 1) & 1) * GSTGH;
            __half* Ws = Xs + 128 * SROWH;
            #pragma unroll
            for (int p = 0; p < 8; p++) {
                int row = crow + p * 16;
                cp16(&Xs[row * SROWH + cc8], A + (size_t)(m0 + row) * D_MOD + k0 + cc8);
            }
            #pragma unroll
            for (int p = 0; p < 4; p++) {
                int row = crow + p * 16;
                cp16(&Ws[row * SROWH + cc8], W + (size_t)(n0 + row) * D_MOD + k0 + cc8);
            }
            CP_COMMIT();
        }

        const unsigned sA = sbase + (it & 1) * (GSTGH * 2);
        const unsigned sB = sA + 128 * 144;

        #pragma unroll
        for (int ks = 0; ks < 4; ks++) {
            unsigned a[4][4], b[2][4];
            #pragma unroll
            for (int mt = 0; mt < 4; mt++)
                ldsm4(a[mt][0], a[mt][1], a[mt][2], a[mt][3],
                      sA + (wm * 64 + mt * 16) * 144 + ks * 32 + aOff);
            #pragma unroll
            for (int np = 0; np < 2; np++)
                ldsm4(b[np][0], b[np][1], b[np][2], b[np][3],
                      sB + (wn * 32 + np * 16) * 144 + ks * 32 + bOff);
            #pragma unroll
            for (int mt = 0; mt < 4; mt++) {
                mma16(acc[mt][0], a[mt][0], a[mt][1], a[mt][2], a[mt][3], b[0][0], b[0][1]);
                mma16(acc[mt][1], a[mt][0], a[mt][1], a[mt][2], a[mt][3], b[0][2], b[0][3]);
                mma16(acc[mt][2], a[mt][0], a[mt][1], a[mt][2], a[mt][3], b[1][0], b[1][1]);
                mma16(acc[mt][3], a[mt][0], a[mt][1], a[mt][2], a[mt][3], b[1][2], b[1][3]);
            }
        }
    }
    __syncthreads();

    #pragma unroll
    for (int mt = 0; mt < 4; mt++) {
        int r0 = m0 + wm * 64 + mt * 16 + g;
        int r1 = r0 + 8;
        if (mode == 1) {
            float* C = (float*)Cv;
            #pragma unroll
            for (int nt = 0; nt < 4; nt++) {
                int col = n0 + wn * 32 + nt * 8 + c * 2;
                *(float2*)(C + (size_t)r0 * D_MOD + col) = make_float2(acc[mt][nt][0], acc[mt][nt][1]);
                *(float2*)(C + (size_t)r1 * D_MOD + col) = make_float2(acc[mt][nt][2], acc[mt][nt][3]);
            }
        } else if (blockIdx.z < 2) {
            // Q/K: RoPE on natural adjacent pairs -> half2 store (fast sincos)
            __half* C = (__half*)Cv;
            float pf0 = (float)tokpos[r0], pf1 = (float)tokpos[r1];
            #pragma unroll
            for (int nt = 0; nt < 4; nt++) {
                int col = n0 + wn * 32 + nt * 8 + 2 * c;
                float x00 = acc[mt][nt][0], x01 = acc[mt][nt][1];
                float x10 = acc[mt][nt][2], x11 = acc[mt][nt][3];
                float freq = g_freq[col >> 1];
                float s0, cs0, s1, cs1;
                __sincosf(pf0 * freq, &s0, &cs0);
                __sincosf(pf1 * freq, &s1, &cs1);
                float y00 = x00 * cs0 - x01 * s0, y01 = x00 * s0 + x01 * cs0;
                float y10 = x10 * cs1 - x11 * s1, y11 = x10 * s1 + x11 * cs1;
                *(__half2*)(C + (size_t)r0 * D_MOD + col) = __floats2half2_rn(y00, y01);
                *(__half2*)(C + (size_t)r1 * D_MOD + col) = __floats2half2_rn(y10, y11);
            }
        } else {
            // V transpose: g_VT[((b*16+h)*64 + d)*2048 + s]
            __half* C = (__half*)Cv;
            int bb = r0 >> 11;
            int s  = r0 & 2047;
            #pragma unroll
            for (int nt = 0; nt < 4; nt++) {
                int n = n0 + wn * 32 + nt * 8 + 2 * c;
                int h = n >> 6, d = n & 63;
                size_t base = ((size_t)((bb << 4) | h) * 64 + d) * 2048;
                C[base        + s    ] = __float2half_rn(acc[mt][nt][0]);
                C[base + 2048 + s    ] = __float2half_rn(acc[mt][nt][1]);   // d+1
                C[base        + s + 8] = __float2half_rn(acc[mt][nt][2]);   // s+8
                C[base + 2048 + s + 8] = __float2half_rn(acc[mt][nt][3]);
            }
        }
    }
}

// ============================================================================
// Fused causal flash attention (round-12 proven). P in registers; Q staged
// through K[1]; fp16 mma + ldmatrix; log2-domain ex2.f16x2 softmax.
// 128 threads, 64 q/CTA, 4 CTAs/SM. smem = 36864 B.
// ============================================================================
#define KSTRH 72
#define TILEH (64 * KSTRH)                     // 4608 halves / tile
#define FK0 0
#define FK1 TILEH
#define FV0 (2 * TILEH)
#define FV1 (3 * TILEH)
#define FLASH_SMEM_BYTES (4 * TILEH * 2)       // 36864

__global__ __launch_bounds__(128, 4)
void flash_attn()
{
    extern __shared__ __align__(16) __half smf[];
    const unsigned sbase = s2u(smf);
    const int tid  = threadIdx.x;
    const int lane = tid & 31;
    const int warp = tid >> 5;
    const int g = lane >> 2;
    const int c = lane & 3;
    const int qt = (S_LEN / 64 - 1) - blockIdx.x;   // heavy tiles first
    const int bh = blockIdx.y;
    const int b = bh >> 4, h = bh & 15;

    const __half* Qg  = g_Q  + ((size_t)(b * S_LEN + qt * 64)) * D_MOD + h * 64;
    const __half* Kg  = g_K  + ((size_t)(b * S_LEN)) * D_MOD + h * 64;
    const __half* VTg = g_VT + ((size_t)((b * 16 + h) * 64)) * 2048;

    const int crow = tid >> 3;          // 0..15
    const int cc8  = (tid & 7) << 3;    // 0..56

    const unsigned aOff = (unsigned)((lane & 15) * 144 + (lane >> 4) * 16);
    const unsigned bOff = (unsigned)(((lane & 7) + ((lane >> 4) << 3)) * 144
                                     + ((lane >> 3) & 1) * 16);

    // prologue: cp.async K0/V0; Q staged into K[1] with plain stores
    #pragma unroll
    for (int p = 0; p < 4; p++) {
        int row = crow + p * 16;
        cp16(&smf[FK0 + row * KSTRH + cc8], Kg  + (size_t)row * D_MOD + cc8);
        cp16(&smf[FV0 + row * KSTRH + cc8], VTg + (size_t)row * 2048 + cc8);
        *(uint4*)&smf[FK1 + row * KSTRH + cc8] =
            *(const uint4*)(Qg + (size_t)row * D_MOD + cc8);
    }
    CP_COMMIT();
    __syncthreads();

    // hoist Q fragments via ldmatrix from K[1] (overwritten at kt=1 prefetch)
    const int qrow0 = warp * 16 + g;
    const int qrow1 = qrow0 + 8;
    unsigned qa[4][4];
    #pragma unroll
    for (int ks = 0; ks < 4; ks++)
        ldsm4(qa[ks][0], qa[ks][1], qa[ks][2], qa[ks][3],
              sbase + FK1 * 2 + (warp * 16) * 144 + ks * 32 + aOff);

    const float CSC = 0.18033688011112042f;   // log2(e)/8
    float m0f = -CUDART_INF_F, m1f = -CUDART_INF_F;
    float l0 = 0.f, l1 = 0.f;
    float o[8][4];
    #pragma unroll
    for (int dt = 0; dt < 8; dt++)
        #pragma unroll
        for (int r = 0; r < 4; r++) o[dt][r] = 0.f;

    for (int kt = 0; kt <= qt; kt++) {
        CP_WAIT0();
        __syncthreads();
        if (kt < qt) {
            int st = (kt + 1) & 1;
            #pragma unroll
            for (int p = 0; p < 4; p++) {
                int row = crow + p * 16;
                cp16(&smf[(st ? FK1 : FK0) + row * KSTRH + cc8],
                     Kg + (size_t)((kt + 1) * 64 + row) * D_MOD + cc8);
                cp16(&smf[(st ? FV1 : FV0) + row * KSTRH + cc8],
                     VTg + (size_t)row * 2048 + (kt + 1) * 64 + cc8);
            }
            CP_COMMIT();
        }
        const unsigned sK = sbase + ((kt & 1) ? FK1 : FK0) * 2;
        const unsigned sV = sbase + ((kt & 1) ? FV1 : FV0) * 2;

        // S = Q @ K^T (raw scores)
        float sacc[8][4];
        #pragma unroll
        for (int nt = 0; nt < 8; nt++)
            #pragma unroll
            for (int r = 0; r < 4; r++) sacc[nt][r] = 0.f;

        #pragma unroll
        for (int ks = 0; ks < 4; ks++) {
            #pragma unroll
            for (int np = 0; np < 4; np++) {
                unsigned b0, b1, b2, b3;
                ldsm4(b0, b1, b2, b3, sK + (np * 16) * 144 + ks * 32 + bOff);
                mma16(sacc[np * 2],     qa[ks][0], qa[ks][1], qa[ks][2], qa[ks][3], b0, b1);
                mma16(sacc[np * 2 + 1], qa[ks][0], qa[ks][1], qa[ks][2], qa[ks][3], b2, b3);
            }
        }

        if (kt == qt) {
            #pragma unroll
            for (int nt = 0; nt < 8; nt++) {
                int k0c = nt * 8 + c * 2, k1c = k0c + 1;
                if (k0c > qrow0) sacc[nt][0] = -CUDART_INF_F;
                if (k1c > qrow0) sacc[nt][1] = -CUDART_INF_F;
                if (k0c > qrow1) sacc[nt][2] = -CUDART_INF_F;
                if (k1c > qrow1) sacc[nt][3] = -CUDART_INF_F;
            }
        }

        float r0 = -CUDART_INF_F, r1 = -CUDART_INF_F;
        #pragma unroll
        for (int nt = 0; nt < 8; nt++) {
            r0 = fmaxf(r0, fmaxf(sacc[nt][0], sacc[nt][1]));
            r1 = fmaxf(r1, fmaxf(sacc[nt][2], sacc[nt][3]));
        }
        r0 = fmaxf(r0, __shfl_xor_sync(0xffffffffu, r0, 1));
        r0 = fmaxf(r0, __shfl_xor_sync(0xffffffffu, r0, 2));
        r1 = fmaxf(r1, __shfl_xor_sync(0xffffffffu, r1, 1));
        r1 = fmaxf(r1, __shfl_xor_sync(0xffffffffu, r1, 2));
        float mn0 = fmaxf(m0f, r0 * CSC), mn1 = fmaxf(m1f, r1 * CSC);
        float al0 = ex2f(m0f - mn0), al1 = ex2f(m1f - mn1);
        m0f = mn0; m1f = mn1;

        // P in registers: pp[nt][0] = (p00,p01) row g; pp[nt][1] = row g+8
        unsigned pp[8][2];
        float rs0 = 0.f, rs1 = 0.f;
        #pragma unroll
        for (int nt = 0; nt < 8; nt++) {
            float t00 = fmaf(sacc[nt][0], CSC, -mn0);
            float t01 = fmaf(sacc[nt][1], CSC, -mn0);
            float t10 = fmaf(sacc[nt][2], CSC, -mn1);
            float t11 = fmaf(sacc[nt][3], CSC, -mn1);
            pp[nt][0] = ex2_h2(pack_h2(t00, t01));
            pp[nt][1] = ex2_h2(pack_h2(t10, t11));
            float2 f0 = __half22float2(*(__half2*)&pp[nt][0]);
            float2 f1 = __half22float2(*(__half2*)&pp[nt][1]);
            rs0 += f0.x + f0.y;
            rs1 += f1.x + f1.y;
        }
        l0 = l0 * al0 + rs0;
        l1 = l1 * al1 + rs1;
        #pragma unroll
        for (int dt = 0; dt < 8; dt++) {
            o[dt][0] *= al0; o[dt][1] *= al0;
            o[dt][2] *= al1; o[dt][3] *= al1;
        }

        // O += P @ V (A-frags directly from pp)
        #pragma unroll
        for (int ks = 0; ks < 4; ks++) {
            #pragma unroll
            for (int dp = 0; dp < 4; dp++) {
                unsigned v0, v1, v2, v3;
                ldsm4(v0, v1, v2, v3, sV + (dp * 16) * 144 + ks * 32 + bOff);
                mma16(o[dp * 2],     pp[2*ks][0], pp[2*ks][1],
                                     pp[2*ks+1][0], pp[2*ks+1][1], v0, v1);
                mma16(o[dp * 2 + 1], pp[2*ks][0], pp[2*ks][1],
                                     pp[2*ks+1][0], pp[2*ks+1][1], v2, v3);
            }
        }
    }

    l0 += __shfl_xor_sync(0xffffffffu, l0, 1);
    l0 += __shfl_xor_sync(0xffffffffu, l0, 2);
    l1 += __shfl_xor_sync(0xffffffffu, l1, 1);
    l1 += __shfl_xor_sync(0xffffffffu, l1, 2);
    float inv0 = 1.f / l0, inv1 = 1.f / l1;

    __half* Og = g_AO + ((size_t)(b * S_LEN + qt * 64)) * D_MOD + h * 64;
    #pragma unroll
    for (int dt = 0; dt < 8; dt++) {
        int pos = dt * 8 + 2 * c;
        *(__half2*)(Og + (size_t)qrow0 * D_MOD + pos) =
            __floats2half2_rn(o[dt][0] * inv0, o[dt][1] * inv0);
        *(__half2*)(Og + (size_t)qrow1 * D_MOD + pos) =
            __floats2half2_rn(o[dt][2] * inv1, o[dt][3] * inv1);
    }
}

// ============================================================================
extern "C" void kernel_launch(void* const* d_in, const int* in_sizes, int n_in,
                              void* d_out, int out_size)
{
    (void)in_sizes; (void)n_in; (void)out_size;
    const float* x  = (const float*)d_in[0];
    const int*   tp = (const int*)d_in[1];
    const float* wq = (const float*)d_in[2];
    const float* wk = (const float*)d_in[3];
    const float* wv = (const float*)d_in[4];
    const float* wo = (const float*)d_in[5];
    float* out = (float*)d_out;

    __half *xptr, *wqp, *wkp, *wvp, *wop, *qptr, *kptr, *vtptr, *aoptr;
    cudaGetSymbolAddress((void**)&xptr,  g_X);
    cudaGetSymbolAddress((void**)&wqp,   g_Wq);
    cudaGetSymbolAddress((void**)&wkp,   g_Wk);
    cudaGetSymbolAddress((void**)&wvp,   g_Wv);
    cudaGetSymbolAddress((void**)&wop,   g_Wo);
    cudaGetSymbolAddress((void**)&qptr,  g_Q);
    cudaGetSymbolAddress((void**)&kptr,  g_K);
    cudaGetSymbolAddress((void**)&vtptr, g_VT);
    cudaGetSymbolAddress((void**)&aoptr, g_AO);

    cudaFuncSetAttribute(gemm_f16, cudaFuncAttributeMaxDynamicSharedMemorySize,
                         GEMM_SMEM_BYTES);
    cudaFuncSetAttribute(flash_attn, cudaFuncAttributeMaxDynamicSharedMemorySize,
                         FLASH_SMEM_BYTES);

    // 0) fp32 -> fp16 + freq table
    preround<<<2048, 256>>>(x, wq, wk, wv, wo);

    // 1) Q/K/V projections (+ fused RoPE on Q,K; V stored transposed)
    dim3 gq(D_MOD / 64, M_TOT / 128, 3);
    gemm_f16<<<gq, 128, GEMM_SMEM_BYTES>>>(xptr, wqp, wkp, wvp,
                                           qptr, kptr, vtptr, tp, 0);

    // 2) fused causal attention
    flash_attn<<<dim3(S_LEN / 64, B_SZ * NH), 128, FLASH_SMEM_BYTES>>>();

    // 3) output projection (fp32 out)
    dim3 go(D_MOD / 64, M_TOT / 128, 1);
    gemm_f16<<<go, 128, GEMM_SMEM_BYTES>>>(aoptr, wop, wop, wop,
                                           out, out, out, nullptr, 1);
}